// round 14
// baseline (speedup 1.0000x reference)
#include <cuda_runtime.h>
#include <cuda_bf16.h>
#include <cstdint>

// Problem constants (fixed by the reference): N=100000, M=8, K=256, D=64
#define PQ_N 100000
#define PQ_M 8
#define PQ_K 256
#define PQ_D 64
#define NTILE 512          // n-rows per block
#define THREADS 256        // 8 warps: (w&3) row-block (128 rows), (w>>2) k-half
#define FLT_BIG 3.402823466e38f

// ---------------- packed f32x2 helpers ----------------
__device__ __forceinline__ unsigned long long pack2(float a) {
    unsigned long long r;
    asm("mov.b64 %0, {%1, %1};" : "=l"(r) : "f"(a));
    return r;
}
__device__ __forceinline__ void ffma2(unsigned long long &d,
                                      unsigned long long a,
                                      unsigned long long b) {
    asm("fma.rn.f32x2 %0, %1, %2, %0;" : "+l"(d) : "l"(a), "l"(b));
}
__device__ __forceinline__ float2 unpack2(unsigned long long v) {
    float2 f;
    asm("mov.b64 {%0, %1}, %2;" : "=f"(f.x), "=f"(f.y) : "l"(v));
    return f;
}

// NEON/LLVM-emulated sum of squares (frozen: matches reference c_sq / x_sq)
__device__ __forceinline__ float neon_sumsq64(const float* v) {
    float a0[4] = {0.f,0.f,0.f,0.f}, a1[4] = {0.f,0.f,0.f,0.f};
    #pragma unroll
    for (int i = 0; i < 8; ++i) {
        #pragma unroll
        for (int l = 0; l < 4; ++l) {
            a0[l] = __fadd_rn(a0[l], __fmul_rn(v[8*i+l],   v[8*i+l]));
            a1[l] = __fadd_rn(a1[l], __fmul_rn(v[8*i+4+l], v[8*i+4+l]));
        }
    }
    float s0 = __fadd_rn(a0[0],a1[0]), s1 = __fadd_rn(a0[1],a1[1]);
    float s2 = __fadd_rn(a0[2],a1[2]), s3 = __fadd_rn(a0[3],a1[3]);
    return __fadd_rn(__fadd_rn(s0,s1), __fadd_rn(s2,s3));
}

// smem layout (floats):
//   cs    [64][256]      transposed codebook                  16384
//   xs    [64][NTILE]    transposed x tile, PRE-NEGATED       32768
//   csq   [256]          ||c_k||^2 (NEON order)                 256
//   scsq  [256]          0.5*||c_k||^2 (acc init)               256
//   xsqs  [NTILE]        ||x_n||^2 (NEON order)                 512
//   mrgf  [2][NTILE][2]  per-half (m1, m2)                     2048
//   mrgi  [2][NTILE][2]  per-half (i1, i2) (as int)            2048
#define SM_CS    0
#define SM_XS    (64 * 256)
#define SM_CSQ   (SM_XS + 64 * NTILE)
#define SM_SCSQ  (SM_CSQ + 256)
#define SM_XSQ   (SM_SCSQ + 256)
#define SM_MRGF  (SM_XSQ + NTILE)
#define SM_MRGI  (SM_MRGF + 2 * NTILE * 2)
#define SM_FLOATS (SM_MRGI + 2 * NTILE * 2)

extern "C" __global__ void __launch_bounds__(THREADS, 1)
pq_r4_kernel(const float* __restrict__ x,
             const float* __restrict__ cb,
             float* __restrict__ qout,
             float* __restrict__ idf,
             long long* __restrict__ idl,
             int id_mode)
{
    extern __shared__ float smem[];
    float* cs   = smem + SM_CS;
    float* xs   = smem + SM_XS;
    float* csq  = smem + SM_CSQ;
    float* scsq = smem + SM_SCSQ;
    float* xsqs = smem + SM_XSQ;
    float* mrgf = smem + SM_MRGF;
    int*   mrgi = reinterpret_cast<int*>(smem + SM_MRGI);

    const int tid  = threadIdx.x;
    const int w    = tid >> 5;
    const int lane = tid & 31;
    const int m    = blockIdx.y;
    const int n0   = blockIdx.x * NTILE;
    const float* cbm = cb + (size_t)m * PQ_K * PQ_D;

    // ---- stage codebook row k=tid: transposed cs; NEON csq; 0.5*csq ----
    {
        const float4* src = reinterpret_cast<const float4*>(cbm + (size_t)tid * PQ_D);
        float cw[64];
        #pragma unroll
        for (int d4 = 0; d4 < 16; ++d4) {
            float4 v = src[d4];
            int d = d4 * 4;
            cw[d+0]=v.x; cw[d+1]=v.y; cw[d+2]=v.z; cw[d+3]=v.w;
            cs[(d+0)*256 + tid] = v.x;
            cs[(d+1)*256 + tid] = v.y;
            cs[(d+2)*256 + tid] = v.z;
            cs[(d+3)*256 + tid] = v.w;
        }
        float sq = neon_sumsq64(cw);
        csq[tid]  = sq;
        scsq[tid] = 0.5f * sq;   // exact power-of-two scale
    }

    // ---- stage x rows tid, tid+256: transposed + PRE-NEGATED; NEON xsq ----
    #pragma unroll
    for (int rr = 0; rr < 2; ++rr) {
        const int row = tid + rr * 256;
        const int n   = n0 + row;
        float xw[64];
        if (n < PQ_N) {
            const float4* gx = reinterpret_cast<const float4*>(
                x + (size_t)n * (PQ_M * PQ_D) + (size_t)m * PQ_D);
            #pragma unroll
            for (int d4 = 0; d4 < 16; ++d4) {
                float4 v = gx[d4];
                xw[d4*4+0]=v.x; xw[d4*4+1]=v.y; xw[d4*4+2]=v.z; xw[d4*4+3]=v.w;
            }
        } else {
            #pragma unroll
            for (int d = 0; d < 64; ++d) xw[d] = 0.f;
        }
        #pragma unroll
        for (int d = 0; d < 64; ++d) xs[d * NTILE + row] = -xw[d];
        xsqs[row] = neon_sumsq64(xw);   // sign-invariant
    }
    __syncthreads();

    // ---- FAST PASS: warp (w&3) owns rows (w&3)*128 + 4*lane + {0..3};
    //      k-half = (w>>2)*128. Chain: acc = 0.5*csq + sum_d (-x_d)*c_d,
    //      d ascending, fused — bit-identical to the R6-verified pass.
    //      5 LDS per 32 FFMA2 (1 x LDS.128 + 4 c LDS.128). ----
    const int half  = w >> 2;
    const int kbase = half * 128;
    const int rb    = (w & 3) * 128 + 4 * lane;   // first of 4 rows

    float m1r[4] = {FLT_BIG, FLT_BIG, FLT_BIG, FLT_BIG};
    float m2r[4] = {FLT_BIG, FLT_BIG, FLT_BIG, FLT_BIG};
    int   i1r[4] = {0,0,0,0}, i2r[4] = {0,0,0,0};

    #pragma unroll 1
    for (int kc = 0; kc < 128; kc += 16) {     // 8 chunks of 8 k-pairs
        unsigned long long acc[4][8];
        {
            const unsigned long long* q0 =
                reinterpret_cast<const unsigned long long*>(scsq + kbase + kc);
            #pragma unroll
            for (int j = 0; j < 8; ++j) {
                unsigned long long q = q0[j];
                acc[0][j] = q; acc[1][j] = q; acc[2][j] = q; acc[3][j] = q;
            }
        }

        #pragma unroll 4
        for (int d = 0; d < 64; ++d) {
            float4 xv = *reinterpret_cast<const float4*>(xs + d * NTILE + rb);
            unsigned long long x0 = pack2(xv.x);   // already -x
            unsigned long long x1 = pack2(xv.y);
            unsigned long long x2 = pack2(xv.z);
            unsigned long long x3 = pack2(xv.w);
            const ulonglong2* cp =
                reinterpret_cast<const ulonglong2*>(cs + d * 256 + kbase + kc);
            #pragma unroll
            for (int jj = 0; jj < 4; ++jj) {
                ulonglong2 c2 = cp[jj];            // one LDS.128 -> 8 FFMA2
                ffma2(acc[0][2*jj],   x0, c2.x);
                ffma2(acc[0][2*jj+1], x0, c2.y);
                ffma2(acc[1][2*jj],   x1, c2.x);
                ffma2(acc[1][2*jj+1], x1, c2.y);
                ffma2(acc[2][2*jj],   x2, c2.x);
                ffma2(acc[2][2*jj+1], x2, c2.y);
                ffma2(acc[3][2*jj],   x3, c2.x);
                ffma2(acc[3][2*jj+1], x3, c2.y);
            }
        }

        // running top-2 per row, ascending k (strict <)
        #pragma unroll
        for (int r = 0; r < 4; ++r) {
            #pragma unroll
            for (int j = 0; j < 8; ++j) {
                float2 s = unpack2(acc[r][j]);
                const int k0 = kbase + kc + 2*j;
                if (s.x < m1r[r])      { m2r[r]=m1r[r]; i2r[r]=i1r[r]; m1r[r]=s.x; i1r[r]=k0; }
                else if (s.x < m2r[r]) { m2r[r]=s.x; i2r[r]=k0; }
                if (s.y < m1r[r])      { m2r[r]=m1r[r]; i2r[r]=i1r[r]; m1r[r]=s.y; i1r[r]=k0+1; }
                else if (s.y < m2r[r]) { m2r[r]=s.y; i2r[r]=k0+1; }
            }
        }
    }

    // ---- publish per-half top-2 (each row owned by 1 thread per half) ----
    #pragma unroll
    for (int r = 0; r < 4; ++r) {
        const int row = rb + r;
        mrgf[(half * NTILE + row) * 2 + 0] = m1r[r];
        mrgf[(half * NTILE + row) * 2 + 1] = m2r[r];
        mrgi[(half * NTILE + row) * 2 + 0] = i1r[r];
        mrgi[(half * NTILE + row) * 2 + 1] = i2r[r];
    }
    __syncthreads();

    // ---- merge + frozen H1 refine + write: thread handles rows tid, tid+256 ----
    #pragma unroll 1
    for (int rr = 0; rr < 2; ++rr) {
        const int row = tid + rr * 256;
        const int n   = n0 + row;

        const float a1 = mrgf[(0 * NTILE + row) * 2 + 0];
        const float a2 = mrgf[(0 * NTILE + row) * 2 + 1];
        const int  ia1 = mrgi[(0 * NTILE + row) * 2 + 0];
        const int  ia2 = mrgi[(0 * NTILE + row) * 2 + 1];
        const float b1 = mrgf[(1 * NTILE + row) * 2 + 0];
        const float b2 = mrgf[(1 * NTILE + row) * 2 + 1];
        const int  ib1 = mrgi[(1 * NTILE + row) * 2 + 0];
        const int  ib2 = mrgi[(1 * NTILE + row) * 2 + 1];

        // merge two sorted pairs; all half0 k < half1 k, ties -> half0
        // (verified R13 logic)
        float best, second; int ibest, isec;
        if (b1 < a1) {
            best = b1; ibest = ib1;
            if (b2 < a1) { second = b2; isec = ib2; }
            else         { second = a1; isec = ia1; }  // tie a1==b2 -> a1 (lower k)
        } else {                                        // tie a1==b1 -> a1
            best = a1; ibest = ia1;
            if (a2 <= b1) { second = a2; isec = ia2; }  // tie a2==b1 -> a2 (lower k)
            else          { second = b1; isec = ib1; }
        }

        // FROZEN H1 refinement (verified exact vs reference): dot = separate
        // rn-mul + rn-add chain over d ascending; dist left-assoc; tie ->
        // lower k. Score-gap 0.75e-3 == dist-gap 1.5e-3 window.
        if (n < PQ_N && (second - best < 0.75e-3f)) {
            const float* xg = x + (size_t)n * (PQ_M * PQ_D) + (size_t)m * PQ_D;
            float ea = 0.f, eb = 0.f;
            #pragma unroll 4
            for (int d = 0; d < 64; ++d) {
                float xv = xg[d];
                ea = __fadd_rn(ea, __fmul_rn(xv, cs[d*256 + ibest]));
                eb = __fadd_rn(eb, __fmul_rn(xv, cs[d*256 + isec]));
            }
            const float xsq = xsqs[row];
            float da = __fadd_rn(__fsub_rn(xsq, __fmul_rn(2.0f, ea)), csq[ibest]);
            float db = __fadd_rn(__fsub_rn(xsq, __fmul_rn(2.0f, eb)), csq[isec]);
            if (db < da || (db == da && isec < ibest)) ibest = isec;
        }

        if (n < PQ_N) {
            // write Q row (selected codeword) from transposed cs
            float* qrow = qout + (size_t)n * (PQ_M * PQ_D) + (size_t)m * PQ_D;
            #pragma unroll
            for (int d4 = 0; d4 < 16; ++d4) {
                float4 v;
                v.x = cs[(d4*4 + 0)*256 + ibest];
                v.y = cs[(d4*4 + 1)*256 + ibest];
                v.z = cs[(d4*4 + 2)*256 + ibest];
                v.w = cs[(d4*4 + 3)*256 + ibest];
                reinterpret_cast<float4*>(qrow)[d4] = v;
            }
            if (id_mode == 1)      idf[(size_t)m * PQ_N + n] = (float)ibest;
            else if (id_mode == 2) idl[(size_t)m * PQ_N + n] = (long long)ibest;
        }
    }
}

extern "C" void kernel_launch(void* const* d_in, const int* in_sizes, int n_in,
                              void* d_out, int out_size) {
    const float* x  = (const float*)d_in[0];   // (N, 512) f32
    const float* cb = (const float*)d_in[1];   // (8, 256, 64) f32

    float* out = (float*)d_out;
    const long long QN  = (long long)PQ_N * PQ_M * PQ_D;  // 51,200,000
    const long long IDN = (long long)PQ_M * PQ_N;         // 800,000

    int id_mode = 0;
    float* idf = nullptr;
    long long* idl = nullptr;
    long long osz = (long long)out_size;
    if (osz >= QN + 2 * IDN) {
        id_mode = 2;
        idl = reinterpret_cast<long long*>(out + QN);
    } else if (osz >= QN + IDN) {
        id_mode = 1;
        idf = out + QN;
    }

    const int smem_bytes = SM_FLOATS * sizeof(float);  // ~212KB
    cudaFuncSetAttribute(pq_r4_kernel,
                         cudaFuncAttributeMaxDynamicSharedMemorySize, smem_bytes);

    dim3 grid((PQ_N + NTILE - 1) / NTILE, PQ_M);
    pq_r4_kernel<<<grid, THREADS, smem_bytes>>>(x, cb, out, idf, idl, id_mode);
}

// round 15
// speedup vs baseline: 1.1431x; 1.1431x over previous
#include <cuda_runtime.h>
#include <cuda_bf16.h>
#include <cstdint>

// Problem constants (fixed by the reference): N=100000, M=8, K=256, D=64
#define PQ_N 100000
#define PQ_M 8
#define PQ_K 256
#define PQ_D 64
#define NTILE 512          // n-rows per block
#define THREADS 512        // 16 warps: (w&3) row-block of 128, (w>>2) k-quarter
#define FLT_BIG 3.402823466e38f

// ---------------- packed f32x2 helpers ----------------
__device__ __forceinline__ unsigned long long pack2(float a) {
    unsigned long long r;
    asm("mov.b64 %0, {%1, %1};" : "=l"(r) : "f"(a));
    return r;
}
__device__ __forceinline__ void ffma2(unsigned long long &d,
                                      unsigned long long a,
                                      unsigned long long b) {
    asm("fma.rn.f32x2 %0, %1, %2, %0;" : "+l"(d) : "l"(a), "l"(b));
}
__device__ __forceinline__ float2 unpack2(unsigned long long v) {
    float2 f;
    asm("mov.b64 {%0, %1}, %2;" : "=f"(f.x), "=f"(f.y) : "l"(v));
    return f;
}

// NEON/LLVM-emulated sum of squares (frozen: matches reference c_sq / x_sq)
__device__ __forceinline__ float neon_sumsq64(const float* v) {
    float a0[4] = {0.f,0.f,0.f,0.f}, a1[4] = {0.f,0.f,0.f,0.f};
    #pragma unroll
    for (int i = 0; i < 8; ++i) {
        #pragma unroll
        for (int l = 0; l < 4; ++l) {
            a0[l] = __fadd_rn(a0[l], __fmul_rn(v[8*i+l],   v[8*i+l]));
            a1[l] = __fadd_rn(a1[l], __fmul_rn(v[8*i+4+l], v[8*i+4+l]));
        }
    }
    float s0 = __fadd_rn(a0[0],a1[0]), s1 = __fadd_rn(a0[1],a1[1]);
    float s2 = __fadd_rn(a0[2],a1[2]), s3 = __fadd_rn(a0[3],a1[3]);
    return __fadd_rn(__fadd_rn(s0,s1), __fadd_rn(s2,s3));
}

// smem layout (floats):
//   cs    [64][256]      transposed codebook                  16384
//   xs    [64][NTILE]    transposed x tile, PRE-NEGATED       32768
//   csq   [256]          ||c_k||^2 (NEON order)                 256
//   scsq  [256]          0.5*||c_k||^2 (acc init)               256
//   xsqs  [NTILE]        ||x_n||^2 (NEON order)                 512
//   mrgf  [4][NTILE][2]  per-quarter (m1, m2)                  4096
//   mrgi  [4][NTILE][2]  per-quarter (i1, i2) as int16         2048
#define SM_CS    0
#define SM_XS    (64 * 256)
#define SM_CSQ   (SM_XS + 64 * NTILE)
#define SM_SCSQ  (SM_CSQ + 256)
#define SM_XSQ   (SM_SCSQ + 256)
#define SM_MRGF  (SM_XSQ + NTILE)
#define SM_MRGI  (SM_MRGF + 4 * NTILE * 2)
#define SM_FLOATS (SM_MRGI + 2 * NTILE * 2)   // int16 array = 2048 floats

extern "C" __global__ void __launch_bounds__(THREADS, 1)
pq_q4_kernel(const float* __restrict__ x,
             const float* __restrict__ cb,
             float* __restrict__ qout,
             float* __restrict__ idf,
             long long* __restrict__ idl,
             int id_mode)
{
    extern __shared__ float smem[];
    float* cs   = smem + SM_CS;
    float* xs   = smem + SM_XS;
    float* csq  = smem + SM_CSQ;
    float* scsq = smem + SM_SCSQ;
    float* xsqs = smem + SM_XSQ;
    float* mrgf = smem + SM_MRGF;
    short* mrgi = reinterpret_cast<short*>(smem + SM_MRGI);

    const int tid  = threadIdx.x;
    const int w    = tid >> 5;
    const int lane = tid & 31;
    const int m    = blockIdx.y;
    const int n0   = blockIdx.x * NTILE;
    const float* cbm = cb + (size_t)m * PQ_K * PQ_D;

    // ---- stage codebook (tid<256): transposed cs; NEON csq; 0.5*csq ----
    if (tid < 256) {
        const float4* src = reinterpret_cast<const float4*>(cbm + (size_t)tid * PQ_D);
        float cw[64];
        #pragma unroll
        for (int d4 = 0; d4 < 16; ++d4) {
            float4 v = src[d4];
            int d = d4 * 4;
            cw[d+0]=v.x; cw[d+1]=v.y; cw[d+2]=v.z; cw[d+3]=v.w;
            cs[(d+0)*256 + tid] = v.x;
            cs[(d+1)*256 + tid] = v.y;
            cs[(d+2)*256 + tid] = v.z;
            cs[(d+3)*256 + tid] = v.w;
        }
        float sq = neon_sumsq64(cw);
        csq[tid]  = sq;
        scsq[tid] = 0.5f * sq;   // exact power-of-two scale
    }

    // ---- stage x row tid: transposed + PRE-NEGATED; NEON xsq ----
    {
        const int n = n0 + tid;
        float xw[64];
        if (n < PQ_N) {
            const float4* gx = reinterpret_cast<const float4*>(
                x + (size_t)n * (PQ_M * PQ_D) + (size_t)m * PQ_D);
            #pragma unroll
            for (int d4 = 0; d4 < 16; ++d4) {
                float4 v = gx[d4];
                xw[d4*4+0]=v.x; xw[d4*4+1]=v.y; xw[d4*4+2]=v.z; xw[d4*4+3]=v.w;
            }
        } else {
            #pragma unroll
            for (int d = 0; d < 64; ++d) xw[d] = 0.f;
        }
        #pragma unroll
        for (int d = 0; d < 64; ++d) xs[d * NTILE + tid] = -xw[d];
        xsqs[tid] = neon_sumsq64(xw);   // sign-invariant
    }
    __syncthreads();

    // ---- FAST PASS: warp (w&3) owns rows (w&3)*128 + 4*lane + {0..3};
    //      k-quarter = (w>>2)*64. Chain: acc = 0.5*csq + sum_d (-x_d)*c_d,
    //      d ascending, fused — bit-identical to the R6-verified pass.
    //      5 LDS per 32 FFMA2 (1 x LDS.128 + 4 c LDS.128). ----
    const int quarter = w >> 2;
    const int kbase   = quarter * 64;
    const int rb      = (w & 3) * 128 + 4 * lane;   // first of 4 rows

    float m1r[4] = {FLT_BIG, FLT_BIG, FLT_BIG, FLT_BIG};
    float m2r[4] = {FLT_BIG, FLT_BIG, FLT_BIG, FLT_BIG};
    int   i1r[4] = {0,0,0,0}, i2r[4] = {0,0,0,0};

    #pragma unroll 1
    for (int kc = 0; kc < 64; kc += 16) {     // 4 chunks of 8 k-pairs
        unsigned long long acc[4][8];
        {
            const unsigned long long* q0 =
                reinterpret_cast<const unsigned long long*>(scsq + kbase + kc);
            #pragma unroll
            for (int j = 0; j < 8; ++j) {
                unsigned long long q = q0[j];
                acc[0][j] = q; acc[1][j] = q; acc[2][j] = q; acc[3][j] = q;
            }
        }

        #pragma unroll 4
        for (int d = 0; d < 64; ++d) {
            float4 xv = *reinterpret_cast<const float4*>(xs + d * NTILE + rb);
            unsigned long long x0 = pack2(xv.x);   // already -x
            unsigned long long x1 = pack2(xv.y);
            unsigned long long x2 = pack2(xv.z);
            unsigned long long x3 = pack2(xv.w);
            const ulonglong2* cp =
                reinterpret_cast<const ulonglong2*>(cs + d * 256 + kbase + kc);
            #pragma unroll
            for (int jj = 0; jj < 4; ++jj) {
                ulonglong2 c2 = cp[jj];            // one LDS.128 -> 8 FFMA2
                ffma2(acc[0][2*jj],   x0, c2.x);
                ffma2(acc[0][2*jj+1], x0, c2.y);
                ffma2(acc[1][2*jj],   x1, c2.x);
                ffma2(acc[1][2*jj+1], x1, c2.y);
                ffma2(acc[2][2*jj],   x2, c2.x);
                ffma2(acc[2][2*jj+1], x2, c2.y);
                ffma2(acc[3][2*jj],   x3, c2.x);
                ffma2(acc[3][2*jj+1], x3, c2.y);
            }
        }

        // running top-2 per row, ascending k (strict <)
        #pragma unroll
        for (int r = 0; r < 4; ++r) {
            #pragma unroll
            for (int j = 0; j < 8; ++j) {
                float2 s = unpack2(acc[r][j]);
                const int k0 = kbase + kc + 2*j;
                if (s.x < m1r[r])      { m2r[r]=m1r[r]; i2r[r]=i1r[r]; m1r[r]=s.x; i1r[r]=k0; }
                else if (s.x < m2r[r]) { m2r[r]=s.x; i2r[r]=k0; }
                if (s.y < m1r[r])      { m2r[r]=m1r[r]; i2r[r]=i1r[r]; m1r[r]=s.y; i1r[r]=k0+1; }
                else if (s.y < m2r[r]) { m2r[r]=s.y; i2r[r]=k0+1; }
            }
        }
    }

    // ---- publish per-quarter top-2 (each row owned by 1 thread/quarter) ----
    #pragma unroll
    for (int r = 0; r < 4; ++r) {
        const int row = rb + r;
        mrgf[(quarter * NTILE + row) * 2 + 0] = m1r[r];
        mrgf[(quarter * NTILE + row) * 2 + 1] = m2r[r];
        mrgi[(quarter * NTILE + row) * 2 + 0] = (short)i1r[r];
        mrgi[(quarter * NTILE + row) * 2 + 1] = (short)i2r[r];
    }
    __syncthreads();

    // ---- merge + frozen H1 refine + write: thread tid owns row tid ----
    {
        const int row = tid;
        const int n   = n0 + row;

        // sequential merge of 4 k-ordered sorted pairs; strict < everywhere
        // keeps ties at the lower k (earlier quarters have lower k).
        float best   = mrgf[(0 * NTILE + row) * 2 + 0];
        float second = mrgf[(0 * NTILE + row) * 2 + 1];
        int   ibest  = mrgi[(0 * NTILE + row) * 2 + 0];
        int   isec   = mrgi[(0 * NTILE + row) * 2 + 1];
        #pragma unroll
        for (int q = 1; q < 4; ++q) {
            const float b1 = mrgf[(q * NTILE + row) * 2 + 0];
            const float b2 = mrgf[(q * NTILE + row) * 2 + 1];
            const int  ib1 = mrgi[(q * NTILE + row) * 2 + 0];
            const int  ib2 = mrgi[(q * NTILE + row) * 2 + 1];
            if (b1 < best) {
                if (b2 < best) { second = b2;   isec = ib2; }
                else           { second = best; isec = ibest; }  // tie -> lower k
                best = b1; ibest = ib1;
            } else if (b1 < second) { second = b1; isec = ib1; }
        }

        // FROZEN H1 refinement (verified exact vs reference): dot = separate
        // rn-mul + rn-add chain over d ascending; dist left-assoc; tie ->
        // lower k. Score-gap 0.75e-3 == dist-gap 1.5e-3 window.
        if (n < PQ_N && (second - best < 0.75e-3f)) {
            const float* xg = x + (size_t)n * (PQ_M * PQ_D) + (size_t)m * PQ_D;
            float ea = 0.f, eb = 0.f;
            #pragma unroll 4
            for (int d = 0; d < 64; ++d) {
                float xv = xg[d];
                ea = __fadd_rn(ea, __fmul_rn(xv, cs[d*256 + ibest]));
                eb = __fadd_rn(eb, __fmul_rn(xv, cs[d*256 + isec]));
            }
            const float xsq = xsqs[row];
            float da = __fadd_rn(__fsub_rn(xsq, __fmul_rn(2.0f, ea)), csq[ibest]);
            float db = __fadd_rn(__fsub_rn(xsq, __fmul_rn(2.0f, eb)), csq[isec]);
            if (db < da || (db == da && isec < ibest)) ibest = isec;
        }

        if (n < PQ_N) {
            // write Q row (selected codeword) from transposed cs
            float* qrow = qout + (size_t)n * (PQ_M * PQ_D) + (size_t)m * PQ_D;
            #pragma unroll
            for (int d4 = 0; d4 < 16; ++d4) {
                float4 v;
                v.x = cs[(d4*4 + 0)*256 + ibest];
                v.y = cs[(d4*4 + 1)*256 + ibest];
                v.z = cs[(d4*4 + 2)*256 + ibest];
                v.w = cs[(d4*4 + 3)*256 + ibest];
                reinterpret_cast<float4*>(qrow)[d4] = v;
            }
            if (id_mode == 1)      idf[(size_t)m * PQ_N + n] = (float)ibest;
            else if (id_mode == 2) idl[(size_t)m * PQ_N + n] = (long long)ibest;
        }
    }
}

extern "C" void kernel_launch(void* const* d_in, const int* in_sizes, int n_in,
                              void* d_out, int out_size) {
    const float* x  = (const float*)d_in[0];   // (N, 512) f32
    const float* cb = (const float*)d_in[1];   // (8, 256, 64) f32

    float* out = (float*)d_out;
    const long long QN  = (long long)PQ_N * PQ_M * PQ_D;  // 51,200,000
    const long long IDN = (long long)PQ_M * PQ_N;         // 800,000

    int id_mode = 0;
    float* idf = nullptr;
    long long* idl = nullptr;
    long long osz = (long long)out_size;
    if (osz >= QN + 2 * IDN) {
        id_mode = 2;
        idl = reinterpret_cast<long long*>(out + QN);
    } else if (osz >= QN + IDN) {
        id_mode = 1;
        idf = out + QN;
    }

    const int smem_bytes = SM_FLOATS * sizeof(float);  // ~220KB
    cudaFuncSetAttribute(pq_q4_kernel,
                         cudaFuncAttributeMaxDynamicSharedMemorySize, smem_bytes);

    dim3 grid((PQ_N + NTILE - 1) / NTILE, PQ_M);
    pq_q4_kernel<<<grid, THREADS, smem_bytes>>>(x, cb, out, idf, idl, id_mode);
}